// round 9
// baseline (speedup 1.0000x reference)
#include <cuda_runtime.h>
#include <cuda_fp16.h>
#include <cstdint>

// ---------------- problem constants ----------------
#define DEGREE   3
#define NB       7
#define NKNOTS   11
#define BATCH    8192
#define IN_DIM   1024
#define OUT_DIM  1024
#define KDIM     (IN_DIM * 8)   // 8192: 7 basis cols + 1 linear col per input

// GEMM tiling: 64x128 CTA tile, 4 warps (2x2) of 32x64, 2-stage cp.async pipeline.
// 48KB smem + <=128 regs -> 4 CTAs/SM resident (16 warps/SM). Per-CTA k-phase
// stagger decorrelates the co-resident CTAs' barriers so tensor pipe stays fed.
#define BM 64
#define BN 128
#define BK 64
#define STAGES 2
#define KITERS (KDIM / BK)      // 128
#define THREADS 128

#define A_STAGE (BM * BK * 2)   // 8192 B
#define B_STAGE (BN * BK * 2)   // 16384 B
#define A_OFF 0
#define B_OFF (STAGES * A_STAGE)                       // 16384
#define SMEM_BYTES (B_OFF + STAGES * B_STAGE + 1024)   // 49152 + align slack

// prep grid split
#define A_BLOCKS 8192            // build-A: 8192 blocks x 256 thr x 4 elems
#define B_TI 16
#define B_TO 32
#define B_BLOCKS ((IN_DIM / B_TI) * (OUT_DIM / B_TO))  // 2048

// ---------------- scratch (device globals; no cudaMalloc allowed) ----------------
__device__ __half g_A[(size_t)BATCH * KDIM];    // 128 MB
__device__ __half g_B[(size_t)OUT_DIM * KDIM];  // 16 MB

// ---------------- PTX helpers (baseline ISA only) ----------------
__device__ __forceinline__ uint32_t smem_u32(const void* p) {
    uint32_t a;
    asm("{ .reg .u64 t; cvta.to.shared.u64 t, %1; cvt.u32.u64 %0, t; }" : "=r"(a) : "l"(p));
    return a;
}
__device__ __forceinline__ void cp_async16(uint32_t sdst, const void* gsrc) {
    asm volatile("cp.async.cg.shared.global [%0], [%1], 16;" :: "r"(sdst), "l"(gsrc));
}
#define CP_COMMIT() asm volatile("cp.async.commit_group;" ::: "memory")
#define CP_WAIT(n)  asm volatile("cp.async.wait_group %0;" :: "n"(n) : "memory")

#define LDSM_X4(r0, r1, r2, r3, addr) \
    asm volatile("ldmatrix.sync.aligned.m8n8.x4.shared.b16 {%0,%1,%2,%3}, [%4];" \
                 : "=r"(r0), "=r"(r1), "=r"(r2), "=r"(r3) : "r"(addr))

#define MMA16816(d, a, b0v, b1v) \
    asm volatile("mma.sync.aligned.m16n8k16.row.col.f32.f16.f16.f32 " \
                 "{%0,%1,%2,%3}, {%4,%5,%6,%7}, {%8,%9}, {%0,%1,%2,%3};" \
                 : "+f"((d)[0]), "+f"((d)[1]), "+f"((d)[2]), "+f"((d)[3]) \
                 : "r"((a)[0]), "r"((a)[1]), "r"((a)[2]), "r"((a)[3]), \
                   "r"(b0v), "r"(b1v))

// ---------------- basis helper ----------------
// FMA-folded recurrence: (t-kn[j])*c == fma(kn[j], -c, t*c) (1-ulp reassociation
// of a continuous weight); degree-0 indicators still compare against the LOADED
// knot values (the truncated basis is discontinuous at knots, so these must match).
__device__ __forceinline__ void eval_row(float xv, const float* kn, __half* h) {
    float e = __expf(2.0f * xv);
    float t = 1.0f - __fdividef(2.0f, e + 1.0f);
    t = fminf(fmaxf(t, kn[0]), kn[NKNOTS - 1]);

    float bas[NB];
#pragma unroll
    for (int j = 0; j < NB; ++j)
        bas[j] = (t >= kn[j] && t < kn[j + 1]) ? 1.0f : 0.0f;

    const float C[3] = {5.0f, 2.5f, 5.0f / 3.0f};
#pragma unroll
    for (int d = 1; d <= DEGREE; ++d) {
        const float c = C[d - 1];
        const float tc = t * c;
#pragma unroll
        for (int j = 0; j < NB; ++j) {
            float left  = __fmaf_rn(kn[j], -c, tc);          // (t-kn[j])*c
            float right = __fmaf_rn(kn[j + d + 1], c, -tc);  // (kn[j+d+1]-t)*c
            float nxt = (j + 1 < NB) ? bas[j + 1] : 0.0f;
            bas[j] = left * bas[j] + right * nxt;
        }
    }
#pragma unroll
    for (int k = 0; k < NB; ++k) h[k] = __float2half_rn(bas[k]);
    h[7] = __float2half_rn(xv);
}

// ---------------- merged prep kernel ----------------
__global__ void __launch_bounds__(256) build_ab_kernel(
    const float* __restrict__ x, const float* __restrict__ knots,
    const float* __restrict__ sw, const float* __restrict__ W)
{
    __shared__ float sw_s[B_TI * 225];      // 16 rows x (224, pad 225)
    __shared__ float w_s[B_TO * 17];        // 32 x 16 (+pad)

    const int tid = threadIdx.x;
    if (blockIdx.x < A_BLOCKS) {
        int base = (blockIdx.x * 256 + tid) * 4;
        float kn[NKNOTS];
#pragma unroll
        for (int j = 0; j < NKNOTS; ++j) kn[j] = __ldg(&knots[j]);
        float4 xv = *reinterpret_cast<const float4*>(x + base);
        __half h[4][8];
        eval_row(xv.x, kn, h[0]);
        eval_row(xv.y, kn, h[1]);
        eval_row(xv.z, kn, h[2]);
        eval_row(xv.w, kn, h[3]);
#pragma unroll
        for (int e = 0; e < 4; ++e)
            *reinterpret_cast<uint4*>(&g_A[(size_t)(base + e) * 8]) =
                *reinterpret_cast<const uint4*>(h[e]);
        return;
    }

    // ---- B part: smem-tiled transpose of spline weights + W ----
    const int bid = blockIdx.x - A_BLOCKS;
    const int i0 = (bid & 63) * B_TI;
    const int o0 = (bid >> 6) * B_TO;

#pragma unroll
    for (int j = 0; j < 14; ++j) {
        int f = tid + j * 256;               // < 3584
        int r = f / 224, c = f % 224;
        sw_s[r * 225 + c] = __ldg(&sw[((size_t)(i0 + r) * OUT_DIM + o0) * NB + c]);
    }
#pragma unroll
    for (int j = 0; j < 2; ++j) {
        int f = tid + j * 256;               // < 512
        int r = f >> 4, c = f & 15;
        w_s[r * 17 + c] = __ldg(&W[(size_t)(o0 + r) * IN_DIM + i0 + c]);
    }
    __syncthreads();

#pragma unroll
    for (int p = 0; p < 2; ++p) {
        int o = (tid >> 4) + p * 16;
        int il = tid & 15;
        __half h[8];
#pragma unroll
        for (int k = 0; k < NB; ++k)
            h[k] = __float2half_rn(sw_s[il * 225 + o * 7 + k]);
        h[7] = __float2half_rn(w_s[o * 17 + il]);
        *reinterpret_cast<uint4*>(&g_B[(size_t)(o0 + o) * KDIM + (size_t)(i0 + il) * 8]) =
            *reinterpret_cast<const uint4*>(h);
    }
}

// ---------------- GEMM: out[M,N] = A[M,K] * Bmat[N,K]^T + bias ----------------
__global__ void __launch_bounds__(THREADS, 4)
kan_gemm_kernel(float* __restrict__ out, const float* __restrict__ bias) {
    extern __shared__ char smem_raw[];
    const uint32_t S = (smem_u32(smem_raw) + 1023u) & ~1023u;

    const int tid  = threadIdx.x;
    const int wid  = tid >> 5;
    const int lane = tid & 31;
    const int wm   = wid >> 1;      // 0..1
    const int wn   = wid & 1;       // 0..1
    const int n0 = blockIdx.x * BN;
    const int m0 = blockIdx.y * BM;

    // per-CTA circular k-phase stagger (decorrelates co-resident CTAs' barriers);
    // accumulation-order rotation only, numerically benign for fp32 accum.
    const int s0 = ((blockIdx.x ^ blockIdx.y) & 3) * (KITERS / 4);

    const __half* gA = g_A + (size_t)m0 * KDIM;
    const __half* gB = g_B + (size_t)n0 * KDIM;

    auto load_stage = [&](int it, int buf) {
        const int k0 = ((s0 + it) & (KITERS - 1)) * BK;
        const uint32_t ab = S + A_OFF + buf * A_STAGE;
#pragma unroll
        for (int t = 0; t < 4; ++t) {               // A: 512 chunks of 16B
            int ch = tid + t * THREADS;
            int row = ch >> 3, cc = ch & 7;
            cp_async16(ab + row * 128 + ((cc * 16) ^ ((row & 7) * 16)),
                       gA + (size_t)row * KDIM + k0 + cc * 8);
        }
        const uint32_t bb = S + B_OFF + buf * B_STAGE;
#pragma unroll
        for (int t = 0; t < 8; ++t) {               // B: 1024 chunks of 16B
            int ch = tid + t * THREADS;
            int row = ch >> 3, cc = ch & 7;
            cp_async16(bb + row * 128 + ((cc * 16) ^ ((row & 7) * 16)),
                       gB + (size_t)row * KDIM + k0 + cc * 8);
        }
        CP_COMMIT();
    };

    uint32_t aRow[2], aXor[2];
#pragma unroll
    for (int mi = 0; mi < 2; ++mi) {
        int row = wm * 32 + mi * 16 + (lane & 15);
        aRow[mi] = (uint32_t)(row * 128);
        aXor[mi] = (uint32_t)((row & 7) * 16);
    }
    const uint32_t aK = ((lane >> 4) * 16);

    uint32_t bRow[4], bXor[4];
#pragma unroll
    for (int g = 0; g < 4; ++g) {
        int row = wn * 64 + g * 16 + ((lane >> 4) << 3) + (lane & 7);
        bRow[g] = (uint32_t)(row * 128);
        bXor[g] = (uint32_t)((row & 7) * 16);
    }
    const uint32_t bK = (((lane >> 3) & 1) * 16);

    float acc[2][8][4];
#pragma unroll
    for (int mi = 0; mi < 2; ++mi)
#pragma unroll
        for (int ni = 0; ni < 8; ++ni)
#pragma unroll
            for (int r = 0; r < 4; ++r) acc[mi][ni][r] = 0.0f;

    load_stage(0, 0);
    load_stage(1, 1);

#pragma unroll 2
    for (int it = 0; it < KITERS; ++it) {
        const int buf = it & 1;
        if (it == KITERS - 1) { CP_WAIT(0); } else { CP_WAIT(1); }
        __syncthreads();

        const uint32_t abase = S + A_OFF + buf * A_STAGE;
        const uint32_t bbase = S + B_OFF + buf * B_STAGE;
#pragma unroll
        for (int kk = 0; kk < 4; ++kk) {
            uint32_t a[2][4];
#pragma unroll
            for (int mi = 0; mi < 2; ++mi)
                LDSM_X4(a[mi][0], a[mi][1], a[mi][2], a[mi][3],
                        abase + aRow[mi] + (((uint32_t)(kk * 32) + aK) ^ aXor[mi]));
            uint32_t b[4][4];
#pragma unroll
            for (int g = 0; g < 4; ++g)
                LDSM_X4(b[g][0], b[g][1], b[g][2], b[g][3],
                        bbase + bRow[g] + (((uint32_t)(kk * 32) + bK) ^ bXor[g]));
#pragma unroll
            for (int mi = 0; mi < 2; ++mi)
#pragma unroll
                for (int g = 0; g < 4; ++g) {
                    MMA16816(acc[mi][2 * g + 0], a[mi], b[g][0], b[g][1]);
                    MMA16816(acc[mi][2 * g + 1], a[mi], b[g][2], b[g][3]);
                }
        }

        const int nxt = it + STAGES;
        if (nxt < KITERS) {
            __syncthreads();             // all warps done reading buf before refill
            load_stage(nxt, buf);
        }
    }

    // ---- epilogue ----
    const int r  = lane >> 2;
    const int c2 = (lane & 3) * 2;
    float bia[8][2];
#pragma unroll
    for (int ni = 0; ni < 8; ++ni) {
        bia[ni][0] = __ldg(&bias[n0 + wn * 64 + ni * 8 + c2 + 0]);
        bia[ni][1] = __ldg(&bias[n0 + wn * 64 + ni * 8 + c2 + 1]);
    }
#pragma unroll
    for (int mi = 0; mi < 2; ++mi) {
        const int mrow = m0 + wm * 32 + mi * 16 + r;
        float* o0 = out + (size_t)mrow * OUT_DIM + n0 + wn * 64;
        float* o1 = o0 + 8 * OUT_DIM;
#pragma unroll
        for (int ni = 0; ni < 8; ++ni) {
            const int nc = ni * 8 + c2;
            float2 v0 = {acc[mi][ni][0] + bia[ni][0], acc[mi][ni][1] + bia[ni][1]};
            float2 v1 = {acc[mi][ni][2] + bia[ni][0], acc[mi][ni][3] + bia[ni][1]};
            *reinterpret_cast<float2*>(o0 + nc) = v0;
            *reinterpret_cast<float2*>(o1 + nc) = v1;
        }
    }
}

// ---------------- launch ----------------
extern "C" void kernel_launch(void* const* d_in, const int* in_sizes, int n_in,
                              void* d_out, int out_size) {
    const float* x     = (const float*)d_in[0];
    const float* sw    = (const float*)d_in[1];
    const float* W     = (const float*)d_in[2];
    const float* bias  = (const float*)d_in[3];
    const float* knots = (const float*)d_in[4];
    float* out = (float*)d_out;

    build_ab_kernel<<<A_BLOCKS + B_BLOCKS, 256>>>(x, knots, sw, W);

    cudaFuncSetAttribute(kan_gemm_kernel, cudaFuncAttributeMaxDynamicSharedMemorySize, SMEM_BYTES);
    dim3 grid(OUT_DIM / BN, BATCH / BM);   // (8, 128) = 1024 CTAs
    kan_gemm_kernel<<<grid, THREADS, SMEM_BYTES>>>(out, bias);
}

// round 10
// speedup vs baseline: 1.0173x; 1.0173x over previous
#include <cuda_runtime.h>
#include <cuda_fp16.h>
#include <cstdint>

// ---------------- problem constants ----------------
#define DEGREE   3
#define NB       7
#define NKNOTS   11
#define BATCH    8192
#define IN_DIM   1024
#define OUT_DIM  1024
#define KDIM     (IN_DIM * 8)   // 8192: 7 basis cols + 1 linear col per input

// GEMM tiling: 64x128 CTA tile, 4 warps (2x2) of 32x64, 2-stage cp.async pipeline.
// 48KB smem + <=128 regs -> 4 CTAs/SM resident (16 warps/SM). NO k-stagger:
// co-resident CTAs of one M-band streaming the same A k-slab is what keeps A
// L2-resident (R9 showed stagger doubles DRAM traffic and loses).
#define BM 64
#define BN 128
#define BK 64
#define STAGES 2
#define KITERS (KDIM / BK)      // 128
#define THREADS 128

#define A_STAGE (BM * BK * 2)   // 8192 B
#define B_STAGE (BN * BK * 2)   // 16384 B
#define A_OFF 0
#define B_OFF (STAGES * A_STAGE)                       // 16384
#define SMEM_BYTES (B_OFF + STAGES * B_STAGE + 1024)   // 49152 + align slack

// prep grid split
#define A_BLOCKS 8192            // build-A: 8192 blocks x 256 thr x 4 elems
#define B_TI 16
#define B_TO 32
#define B_BLOCKS ((IN_DIM / B_TI) * (OUT_DIM / B_TO))  // 2048

// ---------------- scratch (device globals; no cudaMalloc allowed) ----------------
__device__ __half g_A[(size_t)BATCH * KDIM];    // 128 MB
__device__ __half g_B[(size_t)OUT_DIM * KDIM];  // 16 MB

// ---------------- PTX helpers (baseline ISA only) ----------------
__device__ __forceinline__ uint32_t smem_u32(const void* p) {
    uint32_t a;
    asm("{ .reg .u64 t; cvta.to.shared.u64 t, %1; cvt.u32.u64 %0, t; }" : "=r"(a) : "l"(p));
    return a;
}
__device__ __forceinline__ void cp_async16(uint32_t sdst, const void* gsrc) {
    asm volatile("cp.async.cg.shared.global [%0], [%1], 16;" :: "r"(sdst), "l"(gsrc));
}
#define CP_COMMIT() asm volatile("cp.async.commit_group;" ::: "memory")
#define CP_WAIT(n)  asm volatile("cp.async.wait_group %0;" :: "n"(n) : "memory")

#define LDSM_X4(r0, r1, r2, r3, addr) \
    asm volatile("ldmatrix.sync.aligned.m8n8.x4.shared.b16 {%0,%1,%2,%3}, [%4];" \
                 : "=r"(r0), "=r"(r1), "=r"(r2), "=r"(r3) : "r"(addr))

#define MMA16816(d, a, b0v, b1v) \
    asm volatile("mma.sync.aligned.m16n8k16.row.col.f32.f16.f16.f32 " \
                 "{%0,%1,%2,%3}, {%4,%5,%6,%7}, {%8,%9}, {%0,%1,%2,%3};" \
                 : "+f"((d)[0]), "+f"((d)[1]), "+f"((d)[2]), "+f"((d)[3]) \
                 : "r"((a)[0]), "r"((a)[1]), "r"((a)[2]), "r"((a)[3]), \
                   "r"(b0v), "r"(b1v))

// ---------------- basis helper ----------------
// FMA-folded recurrence: (t-kn[j])*c == fma(kn[j], -c, t*c) (1-ulp reassociation
// of a continuous weight); degree-0 indicators still compare against the LOADED
// knot values (the truncated basis is discontinuous at knots, so these must match).
__device__ __forceinline__ void eval_row(float xv, const float* kn, __half* h) {
    float e = __expf(2.0f * xv);
    float t = 1.0f - __fdividef(2.0f, e + 1.0f);
    t = fminf(fmaxf(t, kn[0]), kn[NKNOTS - 1]);

    float bas[NB];
#pragma unroll
    for (int j = 0; j < NB; ++j)
        bas[j] = (t >= kn[j] && t < kn[j + 1]) ? 1.0f : 0.0f;

    const float C[3] = {5.0f, 2.5f, 5.0f / 3.0f};
#pragma unroll
    for (int d = 1; d <= DEGREE; ++d) {
        const float c = C[d - 1];
        const float tc = t * c;
#pragma unroll
        for (int j = 0; j < NB; ++j) {
            float left  = __fmaf_rn(kn[j], -c, tc);          // (t-kn[j])*c
            float right = __fmaf_rn(kn[j + d + 1], c, -tc);  // (kn[j+d+1]-t)*c
            float nxt = (j + 1 < NB) ? bas[j + 1] : 0.0f;
            bas[j] = left * bas[j] + right * nxt;
        }
    }
#pragma unroll
    for (int k = 0; k < NB; ++k) h[k] = __float2half_rn(bas[k]);
    h[7] = __float2half_rn(xv);
}

// ---------------- merged prep kernel ----------------
__global__ void __launch_bounds__(256) build_ab_kernel(
    const float* __restrict__ x, const float* __restrict__ knots,
    const float* __restrict__ sw, const float* __restrict__ W)
{
    __shared__ float sw_s[B_TI * 225];      // 16 rows x (224, pad 225)
    __shared__ float w_s[B_TO * 17];        // 32 x 16 (+pad)

    const int tid = threadIdx.x;
    if (blockIdx.x < A_BLOCKS) {
        int base = (blockIdx.x * 256 + tid) * 4;
        float kn[NKNOTS];
#pragma unroll
        for (int j = 0; j < NKNOTS; ++j) kn[j] = __ldg(&knots[j]);
        float4 xv = *reinterpret_cast<const float4*>(x + base);
        __half h[4][8];
        eval_row(xv.x, kn, h[0]);
        eval_row(xv.y, kn, h[1]);
        eval_row(xv.z, kn, h[2]);
        eval_row(xv.w, kn, h[3]);
#pragma unroll
        for (int e = 0; e < 4; ++e)
            *reinterpret_cast<uint4*>(&g_A[(size_t)(base + e) * 8]) =
                *reinterpret_cast<const uint4*>(h[e]);
        return;
    }

    // ---- B part: smem-tiled transpose of spline weights + W ----
    const int bid = blockIdx.x - A_BLOCKS;
    const int i0 = (bid & 63) * B_TI;
    const int o0 = (bid >> 6) * B_TO;

#pragma unroll
    for (int j = 0; j < 14; ++j) {
        int f = tid + j * 256;               // < 3584
        int r = f / 224, c = f % 224;
        sw_s[r * 225 + c] = __ldg(&sw[((size_t)(i0 + r) * OUT_DIM + o0) * NB + c]);
    }
#pragma unroll
    for (int j = 0; j < 2; ++j) {
        int f = tid + j * 256;               // < 512
        int r = f >> 4, c = f & 15;
        w_s[r * 17 + c] = __ldg(&W[(size_t)(o0 + r) * IN_DIM + i0 + c]);
    }
    __syncthreads();

#pragma unroll
    for (int p = 0; p < 2; ++p) {
        int o = (tid >> 4) + p * 16;
        int il = tid & 15;
        __half h[8];
#pragma unroll
        for (int k = 0; k < NB; ++k)
            h[k] = __float2half_rn(sw_s[il * 225 + o * 7 + k]);
        h[7] = __float2half_rn(w_s[o * 17 + il]);
        *reinterpret_cast<uint4*>(&g_B[(size_t)(o0 + o) * KDIM + (size_t)(i0 + il) * 8]) =
            *reinterpret_cast<const uint4*>(h);
    }
}

// ---------------- GEMM: out[M,N] = A[M,K] * Bmat[N,K]^T + bias ----------------
__global__ void __launch_bounds__(THREADS, 4)
kan_gemm_kernel(float* __restrict__ out, const float* __restrict__ bias) {
    extern __shared__ char smem_raw[];
    const uint32_t S = (smem_u32(smem_raw) + 1023u) & ~1023u;

    const int tid  = threadIdx.x;
    const int wid  = tid >> 5;
    const int lane = tid & 31;
    const int wm   = wid >> 1;      // 0..1
    const int wn   = wid & 1;       // 0..1
    const int n0 = blockIdx.x * BN;
    const int m0 = blockIdx.y * BM;

    const __half* gA = g_A + (size_t)m0 * KDIM;
    const __half* gB = g_B + (size_t)n0 * KDIM;

    auto load_stage = [&](int it, int buf) {
        const int k0 = it * BK;
        const uint32_t ab = S + A_OFF + buf * A_STAGE;
#pragma unroll
        for (int t = 0; t < 4; ++t) {               // A: 512 chunks of 16B
            int ch = tid + t * THREADS;
            int row = ch >> 3, cc = ch & 7;
            cp_async16(ab + row * 128 + ((cc * 16) ^ ((row & 7) * 16)),
                       gA + (size_t)row * KDIM + k0 + cc * 8);
        }
        const uint32_t bb = S + B_OFF + buf * B_STAGE;
#pragma unroll
        for (int t = 0; t < 8; ++t) {               // B: 1024 chunks of 16B
            int ch = tid + t * THREADS;
            int row = ch >> 3, cc = ch & 7;
            cp_async16(bb + row * 128 + ((cc * 16) ^ ((row & 7) * 16)),
                       gB + (size_t)row * KDIM + k0 + cc * 8);
        }
        CP_COMMIT();
    };

    uint32_t aRow[2], aXor[2];
#pragma unroll
    for (int mi = 0; mi < 2; ++mi) {
        int row = wm * 32 + mi * 16 + (lane & 15);
        aRow[mi] = (uint32_t)(row * 128);
        aXor[mi] = (uint32_t)((row & 7) * 16);
    }
    const uint32_t aK = ((lane >> 4) * 16);

    uint32_t bRow[4], bXor[4];
#pragma unroll
    for (int g = 0; g < 4; ++g) {
        int row = wn * 64 + g * 16 + ((lane >> 4) << 3) + (lane & 7);
        bRow[g] = (uint32_t)(row * 128);
        bXor[g] = (uint32_t)((row & 7) * 16);
    }
    const uint32_t bK = (((lane >> 3) & 1) * 16);

    float acc[2][8][4];
#pragma unroll
    for (int mi = 0; mi < 2; ++mi)
#pragma unroll
        for (int ni = 0; ni < 8; ++ni)
#pragma unroll
            for (int r = 0; r < 4; ++r) acc[mi][ni][r] = 0.0f;

    load_stage(0, 0);
    load_stage(1, 1);

#pragma unroll 2
    for (int it = 0; it < KITERS; ++it) {
        const int buf = it & 1;
        if (it == KITERS - 1) { CP_WAIT(0); } else { CP_WAIT(1); }
        __syncthreads();

        const uint32_t abase = S + A_OFF + buf * A_STAGE;
        const uint32_t bbase = S + B_OFF + buf * B_STAGE;
#pragma unroll
        for (int kk = 0; kk < 4; ++kk) {
            uint32_t a[2][4];
#pragma unroll
            for (int mi = 0; mi < 2; ++mi)
                LDSM_X4(a[mi][0], a[mi][1], a[mi][2], a[mi][3],
                        abase + aRow[mi] + (((uint32_t)(kk * 32) + aK) ^ aXor[mi]));
            uint32_t b[4][4];
#pragma unroll
            for (int g = 0; g < 4; ++g)
                LDSM_X4(b[g][0], b[g][1], b[g][2], b[g][3],
                        bbase + bRow[g] + (((uint32_t)(kk * 32) + bK) ^ bXor[g]));
#pragma unroll
            for (int mi = 0; mi < 2; ++mi)
#pragma unroll
                for (int g = 0; g < 4; ++g) {
                    MMA16816(acc[mi][2 * g + 0], a[mi], b[g][0], b[g][1]);
                    MMA16816(acc[mi][2 * g + 1], a[mi], b[g][2], b[g][3]);
                }
        }

        const int nxt = it + STAGES;
        if (nxt < KITERS) {
            __syncthreads();             // all warps done reading buf before refill
            load_stage(nxt, buf);
        }
    }

    // ---- epilogue ----
    const int r  = lane >> 2;
    const int c2 = (lane & 3) * 2;
    float bia[8][2];
#pragma unroll
    for (int ni = 0; ni < 8; ++ni) {
        bia[ni][0] = __ldg(&bias[n0 + wn * 64 + ni * 8 + c2 + 0]);
        bia[ni][1] = __ldg(&bias[n0 + wn * 64 + ni * 8 + c2 + 1]);
    }
#pragma unroll
    for (int mi = 0; mi < 2; ++mi) {
        const int mrow = m0 + wm * 32 + mi * 16 + r;
        float* o0 = out + (size_t)mrow * OUT_DIM + n0 + wn * 64;
        float* o1 = o0 + 8 * OUT_DIM;
#pragma unroll
        for (int ni = 0; ni < 8; ++ni) {
            const int nc = ni * 8 + c2;
            float2 v0 = {acc[mi][ni][0] + bia[ni][0], acc[mi][ni][1] + bia[ni][1]};
            float2 v1 = {acc[mi][ni][2] + bia[ni][0], acc[mi][ni][3] + bia[ni][1]};
            *reinterpret_cast<float2*>(o0 + nc) = v0;
            *reinterpret_cast<float2*>(o1 + nc) = v1;
        }
    }
}

// ---------------- launch ----------------
extern "C" void kernel_launch(void* const* d_in, const int* in_sizes, int n_in,
                              void* d_out, int out_size) {
    const float* x     = (const float*)d_in[0];
    const float* sw    = (const float*)d_in[1];
    const float* W     = (const float*)d_in[2];
    const float* bias  = (const float*)d_in[3];
    const float* knots = (const float*)d_in[4];
    float* out = (float*)d_out;

    build_ab_kernel<<<A_BLOCKS + B_BLOCKS, 256>>>(x, knots, sw, W);

    cudaFuncSetAttribute(kan_gemm_kernel, cudaFuncAttributeMaxDynamicSharedMemorySize, SMEM_BYTES);
    dim3 grid(OUT_DIM / BN, BATCH / BM);   // (8, 128) = 1024 CTAs
    kan_gemm_kernel<<<grid, THREADS, SMEM_BYTES>>>(out, bias);
}